// round 15
// baseline (speedup 1.0000x reference)
#include <cuda_runtime.h>
#include <math.h>

#define BB 4
#define NN 20000
#define MM 1024
#define CAP 1024
#define KSEL 50
#define SEL_BLOCKS 512   // k_select blocks (8 warps = 8 nodes each)

#define SUB 32           // kp sub-block for argmin rescan
#define NSUB 32          // MM/SUB
#define SKW 33           // float4 stride per sub-block (32 + 1 skew)

typedef unsigned long long ull;

// scratch (device globals — allocation-free). BSS zero at process start;
// the last k_select block re-zeros g_count/g_sum/g_ticket every launch.
__device__ int    g_count[BB*MM];
__device__ int    g_p2n[BB*NN];
__device__ float  g_tp[BB*NN*3];
__device__ ull    g_bkey[BB*MM*CAP];        // packed (orderable dist, idx)
__device__ long long g_sum[BB*MM*3];        // Q32 per-node sums of tp
__device__ long long g_pnum[SEL_BLOCKS];
__device__ long long g_pden[SEL_BLOCKS];
__device__ unsigned g_ticket;

__device__ __forceinline__ ull f2fma(ull a, ull b, ull c) {
    ull d;
    asm("fma.rn.f32x2 %0, %1, %2, %3;" : "=l"(d) : "l"(a), "l"(b), "l"(c));
    return d;
}
__device__ __forceinline__ ull packf2(float lo, float hi) {
    ull d;
    asm("mov.b64 %0, {%1, %2};" : "=l"(d) : "f"(lo), "f"(hi));
    return d;
}
__device__ __forceinline__ float2 unpackf2(ull v) {
    float2 f;
    asm("mov.b64 {%0, %1}, %2;" : "=f"(f.x), "=f"(f.y) : "l"(v));
    return f;
}
// orderable packing of (dist, idx): u64 ascending == (dist, idx) lexicographic
__device__ __forceinline__ ull packdi(float d, int i) {
    unsigned int b = __float_as_uint(d);
    b = (b & 0x80000000u) ? ~b : (b | 0x80000000u);
    return ((ull)b << 32) | (unsigned int)i;
}
#define Q32 4294967296.0
__device__ __forceinline__ long long toq32(float x) {
    return (long long)rint((double)x * Q32);
}

// ---------------------------------------------------------------------------
// Kernel 1: nearest keypoint per point. 2 points/thread; keypoints duplicated
// in smem (sA=(−2x,−2x,−2y,−2y), sB=(−2z,−2z,ss,ss)) so the inner loop is
// 2 LDS.128 + 3 FFMA2 + 2 FMNMX per kp for BOTH points — min-only, no index
// tracking. Sub-block (32) winners are rescanned with the identical fma order
// (bit-exact) to recover the first-occurrence argmin. Layout skewed 16B per
// sub-block so rescans across lanes are bank-staggered. The epilogue
// accumulates each point's transformed coords into per-node Q32 integer sums
// (order-free atomics => deterministic).
// ---------------------------------------------------------------------------
__global__ void __launch_bounds__(128) k_assign(const float* __restrict__ pts,
                                                const float* __restrict__ kp,
                                                const float* __restrict__ pose) {
    __shared__ float4 sA[MM + NSUB];   // skewed: idx = m + (m>>5)
    __shared__ float4 sB[MM + NSUB];

    const int b = blockIdx.y;
    const float* kpb = kp + (size_t)b * MM * 3;
    for (int i = threadIdx.x; i < MM; i += 128) {
        float x = kpb[3*i+0], y = kpb[3*i+1], z = kpb[3*i+2];
        float ss = fmaf(x,x, fmaf(y,y, z*z));
        int ix = i + (i >> 5);
        sA[ix] = make_float4(-2.f*x, -2.f*x, -2.f*y, -2.f*y);
        sB[ix] = make_float4(-2.f*z, -2.f*z, ss, ss);
    }
    __syncthreads();

    const int t  = blockIdx.x * 128 + threadIdx.x;
    const int n0 = t * 2;
    if (n0 >= NN) return;

    const float* p = pts + ((size_t)b * NN + n0) * 3;
    const float2 q0 = ((const float2*)p)[0];   // x0 y0
    const float2 q1 = ((const float2*)p)[1];   // z0 x1
    const float2 q2 = ((const float2*)p)[2];   // y1 z1
    const float px0 = q0.x, py0 = q0.y, pz0 = q1.x;
    const float px1 = q1.y, py1 = q2.x, pz1 = q2.y;

    const ull px2 = packf2(px0, px1);
    const ull py2 = packf2(py0, py1);
    const ull pz2 = packf2(pz0, pz1);

    float best0 = 3.4e38f, best1 = 3.4e38f;
    int   blk0 = 0, blk1 = 0;

    for (int sb = 0; sb < NSUB; sb++) {
        const ulonglong2* __restrict__ A2 = (const ulonglong2*)(sA + sb * SKW);
        const ulonglong2* __restrict__ B2 = (const ulonglong2*)(sB + sb * SKW);
        float l0 = 3.4e38f, l1 = 3.4e38f;
        #pragma unroll
        for (int mm = 0; mm < SUB; mm++) {
            ulonglong2 a = A2[mm];      // (kx2, ky2)
            ulonglong2 c = B2[mm];      // (kz2, kw2)
            ull acc = f2fma(a.x, px2, c.y);
            acc = f2fma(a.y, py2, acc);
            acc = f2fma(c.x, pz2, acc);
            float2 f = unpackf2(acc);
            l0 = fminf(l0, f.x);
            l1 = fminf(l1, f.y);
        }
        if (l0 < best0) { best0 = l0; blk0 = sb; }
        if (l1 < best1) { best1 = l1; blk1 = sb; }
    }

    // exact index recovery: rescan winning sub-block, identical fma order
    int bi0 = 0x7fffffff, bi1 = 0x7fffffff;
    {
        const float4* a4 = sA + blk0 * SKW;
        const float4* b4 = sB + blk0 * SKW;
        #pragma unroll 8
        for (int mm = 0; mm < SUB; mm++) {
            float4 a = a4[mm];
            float4 c = b4[mm];
            float s = fmaf(c.x, pz0, fmaf(a.z, py0, fmaf(a.x, px0, c.z)));
            if (s == best0) bi0 = min(bi0, blk0 * SUB + mm);
        }
    }
    {
        const float4* a4 = sA + blk1 * SKW;
        const float4* b4 = sB + blk1 * SKW;
        #pragma unroll 8
        for (int mm = 0; mm < SUB; mm++) {
            float4 a = a4[mm];
            float4 c = b4[mm];
            float s = fmaf(c.x, pz1, fmaf(a.z, py1, fmaf(a.x, px1, c.z)));
            if (s == best1) bi1 = min(bi1, blk1 * SUB + mm);
        }
    }

    const float* P = pose + b * 16;
    float R00=P[0],R01=P[1],R02=P[2],T0=P[3];
    float R10=P[4],R11=P[5],R12=P[6],T1=P[7];
    float R20=P[8],R21=P[9],R22=P[10],T2=P[11];

    float t0x = fmaf(R00,px0, fmaf(R01,py0, fmaf(R02,pz0, T0)));
    float t0y = fmaf(R10,px0, fmaf(R11,py0, fmaf(R12,pz0, T1)));
    float t0z = fmaf(R20,px0, fmaf(R21,py0, fmaf(R22,pz0, T2)));
    float t1x = fmaf(R00,px1, fmaf(R01,py1, fmaf(R02,pz1, T0)));
    float t1y = fmaf(R10,px1, fmaf(R11,py1, fmaf(R12,pz1, T1)));
    float t1z = fmaf(R20,px1, fmaf(R21,py1, fmaf(R22,pz1, T2)));

    // point 0
    {
        float psq = fmaf(px0,px0, fmaf(py0,py0, pz0*pz0));
        float dist = best0 + psq;
        g_p2n[b*NN + n0] = bi0;
        int node = b*MM + bi0;
        int pos = atomicAdd(&g_count[node], 1);
        if (pos < CAP) g_bkey[(size_t)node * CAP + pos] = packdi(dist, n0);
        atomicAdd((ull*)&g_sum[node*3+0], (ull)toq32(t0x));
        atomicAdd((ull*)&g_sum[node*3+1], (ull)toq32(t0y));
        atomicAdd((ull*)&g_sum[node*3+2], (ull)toq32(t0z));
    }
    // point 1
    {
        float psq = fmaf(px1,px1, fmaf(py1,py1, pz1*pz1));
        float dist = best1 + psq;
        g_p2n[b*NN + n0 + 1] = bi1;
        int node = b*MM + bi1;
        int pos = atomicAdd(&g_count[node], 1);
        if (pos < CAP) g_bkey[(size_t)node * CAP + pos] = packdi(dist, n0 + 1);
        atomicAdd((ull*)&g_sum[node*3+0], (ull)toq32(t1x));
        atomicAdd((ull*)&g_sum[node*3+1], (ull)toq32(t1y));
        atomicAdd((ull*)&g_sum[node*3+2], (ull)toq32(t1z));
    }

    float2* tv = (float2*)(g_tp + ((size_t)b * NN + n0) * 3);
    tv[0] = make_float2(t0x, t0y);
    tv[1] = make_float2(t0z, t1x);
    tv[2] = make_float2(t1y, t1z);
}

// ---- warp bitonic helpers: 64 keys in (v0 rank=lane, v1 rank=32+lane) ----
__device__ __forceinline__ void bsort64(ull& v0, ull& v1, int lane) {
    #pragma unroll
    for (int k = 2; k <= 32; k <<= 1) {
        #pragma unroll
        for (int j = k >> 1; j >= 1; j >>= 1) {
            bool up0 = ((lane & k) == 0);
            bool up1 = (((lane + 32) & k) == 0);
            bool low = ((lane & j) == 0);
            ull o0 = __shfl_xor_sync(0xffffffffu, v0, j);
            ull o1 = __shfl_xor_sync(0xffffffffu, v1, j);
            v0 = (low == up0) ? min(v0, o0) : max(v0, o0);
            v1 = (low == up1) ? min(v1, o1) : max(v1, o1);
        }
    }
    ull lo_ = min(v0, v1), hi_ = max(v0, v1); v0 = lo_; v1 = hi_;
    #pragma unroll
    for (int j = 16; j >= 1; j >>= 1) {
        bool low = ((lane & j) == 0);
        ull o0 = __shfl_xor_sync(0xffffffffu, v0, j);
        ull o1 = __shfl_xor_sync(0xffffffffu, v1, j);
        v0 = low ? min(v0, o0) : max(v0, o0);
        v1 = low ? min(v1, o1) : max(v1, o1);
    }
}
__device__ __forceinline__ void bmerge_low64(ull& v0, ull& v1, ull t0, ull t1,
                                             int lane) {
    ull r0 = __shfl_xor_sync(0xffffffffu, t1, 31);
    ull r1 = __shfl_xor_sync(0xffffffffu, t0, 31);
    v0 = min(v0, r0);
    v1 = min(v1, r1);
    ull lo_ = min(v0, v1), hi_ = max(v0, v1); v0 = lo_; v1 = hi_;
    #pragma unroll
    for (int j = 16; j >= 1; j >>= 1) {
        bool low = ((lane & j) == 0);
        ull o0 = __shfl_xor_sync(0xffffffffu, v0, j);
        ull o1 = __shfl_xor_sync(0xffffffffu, v1, j);
        v0 = low ? min(v0, o0) : max(v0, o0);
        v1 = low ? min(v1, o1) : max(v1, o1);
    }
}

// ---------------------------------------------------------------------------
// Kernel 2: ONE WARP PER NODE (8 nodes/block). Fast path (c<=50): the member
// sum is ALREADY in g_sum (deterministic integer) — only the padding ballot
// scan remains. Slow path (c>50, rare): streaming bitonic top-64 over keys.
// Fused deterministic final reduction via atomic ticket.
// ---------------------------------------------------------------------------
__global__ void __launch_bounds__(256) k_select(const float* __restrict__ kpw,
                                                const float* __restrict__ ow,
                                                float* __restrict__ out) {
    __shared__ long long s_num[8];
    __shared__ long long s_den[8];
    __shared__ int s_last;

    const int warp = threadIdx.x >> 5;
    const int lane = threadIdx.x & 31;
    const int id   = blockIdx.x * 8 + warp;
    const int b    = id >> 10;
    const int m    = id & (MM - 1);

    const int c  = g_count[id];
    const float* tpf = g_tp + (size_t)b * NN * 3;

    float sx, sy, sz;

    if (c <= KSEL) {
        // member sum from precomputed order-free integer accumulators
        sx = (float)((double)g_sum[id*3+0] * (1.0 / Q32));
        sy = (float)((double)g_sum[id*3+1] * (1.0 / Q32));
        sz = (float)((double)g_sum[id*3+2] * (1.0 / Q32));

        // pad with smallest UNassigned indices (ballot scan, fixed butterfly)
        int k = KSEL - c;
        const int* p2n = &g_p2n[b * NN];
        int n0 = 0;
        while (k > 0) {
            int n = n0 + lane;
            int pm = (n < NN) ? p2n[n] : m;
            bool un = (pm != m);
            unsigned mask = __ballot_sync(0xffffffffu, un);
            int cnt  = __popc(mask);
            int take = min(k, cnt);
            int rank = __popc(mask & ((1u << lane) - 1u));
            bool sel = un && (rank < take);
            float tx = 0.f, ty = 0.f, tz = 0.f;
            if (sel) {
                const float* tt = tpf + (size_t)n * 3;
                tx = tt[0]; ty = tt[1]; tz = tt[2];
            }
            #pragma unroll
            for (int off = 16; off > 0; off >>= 1) {
                tx += __shfl_xor_sync(0xffffffffu, tx, off);
                ty += __shfl_xor_sync(0xffffffffu, ty, off);
                tz += __shfl_xor_sync(0xffffffffu, tz, off);
            }
            sx += tx; sy += ty; sz += tz;
            k -= take;
            n0 += 32;
        }
    } else {
        // streaming bitonic top-64 by (dist,idx); sum smallest 50 (canonical
        // sorted order => deterministic)
        const int cc = min(c, CAP);
        const ull* bkey = &g_bkey[(size_t)id * CAP];
        const ull UMAX = 0xffffffffffffffffull;
        ull v0 = (lane      < cc) ? bkey[lane]      : UMAX;
        ull v1 = (lane + 32 < cc) ? bkey[lane + 32] : UMAX;
        bsort64(v0, v1, lane);
        for (int base = 64; base < cc; base += 64) {
            ull t0 = (base + lane      < cc) ? bkey[base + lane]      : UMAX;
            ull t1 = (base + lane + 32 < cc) ? bkey[base + lane + 32] : UMAX;
            bsort64(t0, t1, lane);
            bmerge_low64(v0, v1, t0, t1, lane);
        }
        float ax, ay, az;
        {
            int i0 = (int)(unsigned)v0;
            const float* tt = tpf + (size_t)i0 * 3;
            ax = tt[0]; ay = tt[1]; az = tt[2];
        }
        if (lane + 32 <= KSEL - 1) {
            int i1 = (int)(unsigned)v1;
            const float* tt = tpf + (size_t)i1 * 3;
            ax += tt[0]; ay += tt[1]; az += tt[2];
        }
        #pragma unroll
        for (int off = 16; off > 0; off >>= 1) {
            ax += __shfl_xor_sync(0xffffffffu, ax, off);
            ay += __shfl_xor_sync(0xffffffffu, ay, off);
            az += __shfl_xor_sync(0xffffffffu, az, off);
        }
        sx = ax; sy = ay; sz = az;
    }

    if (lane == 0) {
        const float inv = 1.0f / (float)KSEL;
        const float* kw = kpw + (size_t)id * 3;
        float ex = sx * inv - kw[0];
        float ey = sy * inv - kw[1];
        float ez = sz * inv - kw[2];
        float l1 = fabsf(ex) + fabsf(ey) + fabsf(ez);
        double w = (double)ow[id];
        s_num[warp] = (long long)(w * (double)l1 * Q32);
        s_den[warp] = (long long)(w * Q32);
    }
    __syncthreads();
    if (threadIdx.x == 0) {
        long long n = 0, d = 0;
        #pragma unroll
        for (int i = 0; i < 8; i++) { n += s_num[i]; d += s_den[i]; }
        g_pnum[blockIdx.x] = n;
        g_pden[blockIdx.x] = d;
        __threadfence();
        s_last = (atomicAdd(&g_ticket, 1u) == (unsigned)(gridDim.x - 1));
    }
    __syncthreads();

    if (s_last) {
        __shared__ long long rn[256];
        __shared__ long long rd[256];
        const int t = threadIdx.x;
        rn[t] = g_pnum[t] + g_pnum[t + 256];
        rd[t] = g_pden[t] + g_pden[t + 256];
        __syncthreads();
        for (int s = 128; s > 0; s >>= 1) {
            if (t < s) { rn[t] += rn[t + s]; rd[t] += rd[t + s]; }
            __syncthreads();
        }
        if (t == 0) {
            double num = (double)rn[0] * (1.0 / Q32);
            double den = (double)rd[0] * (1.0 / Q32);
            out[0] = (float)(num / fmax(den, 1e-6));
        }
        // restore invariants for the next launch / graph replay
        for (int i = t; i < BB*MM; i += 256)   g_count[i] = 0;
        for (int i = t; i < BB*MM*3; i += 256) g_sum[i] = 0;
        __syncthreads();
        if (t == 0) g_ticket = 0;
    }
}

extern "C" void kernel_launch(void* const* d_in, const int* in_sizes, int n_in,
                              void* d_out, int out_size) {
    const float* pts  = (const float*)d_in[0];  // (B,N,3)
    const float* kp   = (const float*)d_in[1];  // (B,M,3)
    const float* kpw  = (const float*)d_in[2];  // (B,M,3)
    const float* pose = (const float*)d_in[3];  // (B,4,4)
    const float* ow   = (const float*)d_in[4];  // (B,M)
    float* out = (float*)d_out;

    dim3 g1((NN/2 + 127) / 128, BB);            // 79 x 4 blocks, 128 threads
    k_assign<<<g1, 128>>>(pts, kp, pose);

    k_select<<<SEL_BLOCKS, 256>>>(kpw, ow, out);
}